// round 15
// baseline (speedup 1.0000x reference)
#include <cuda_runtime.h>

#define NQ 4
#define NL 8
#define NGATES ((NL + 1) * NQ)

typedef unsigned long long ull;

// ---------- packed f32x2 helpers (Blackwell FFMA2 path) ----------
__device__ __forceinline__ ull pk2(float lo, float hi) {
    ull r; asm("mov.b64 %0, {%1,%2};" : "=l"(r) : "f"(lo), "f"(hi)); return r;
}
__device__ __forceinline__ ull bc2(float x) { return pk2(x, x); }
__device__ __forceinline__ void up2(ull v, float& lo, float& hi) {
    asm("mov.b64 {%0,%1}, %2;" : "=f"(lo), "=f"(hi) : "l"(v));
}
__device__ __forceinline__ ull fma2(ull a, ull b, ull c) {
    ull d; asm("fma.rn.f32x2 %0, %1, %2, %3;" : "=l"(d) : "l"(a), "l"(b), "l"(c)); return d;
}
__device__ __forceinline__ ull mul2(ull a, ull b) {
    ull d; asm("mul.rn.f32x2 %0, %1, %2;" : "=l"(d) : "l"(a), "l"(b)); return d;
}
__device__ __forceinline__ ull swap2(ull v) { float l, h; up2(v, l, h); return pk2(h, l); }

#define SGN_LO 0x0000000080000000ULL   // flip lo lane only
#define SGN_HI 0x8000000000000000ULL   // flip hi lane only

// SU(2) gates: U = [[a, b], [-conj(b), conj(a)]]. Store only (ar, ai, br, bi).
__device__ float4 g_gates[NGATES];

__global__ void precompute_gates_kernel(const float* __restrict__ theta) {
    int g = blockIdx.x * blockDim.x + threadIdx.x;
    if (g >= NGATES) return;
    float a = theta[g * 3 + 0];
    float b = theta[g * 3 + 1];
    float c = theta[g * 3 + 2];
    float sa, ca, sb, cb, sc, cc;
    sincosf(0.5f * a, &sa, &ca);
    sincosf(0.5f * b, &sb, &cb);
    sincosf(0.5f * c, &sc, &cc);
    float m00r = cb * ca, m00i =  sb * sa;
    float m01r = -sb * ca, m01i = -cb * sa;
    float4 o;
    o.x = m00r * cc + m00i * sc;   // u00r
    o.y = m00i * cc - m00r * sc;   // u00i
    o.z = m01r * cc + m01i * sc;   // u01r
    o.w = m01i * cc - m01r * sc;   // u01i
    g_gates[g] = o;
}

// SU(2) pair apply: V = [[v0+iv1, v2+iv3], [-v2+iv3, v0-iv1]]
__device__ __forceinline__ void appS(ull* R, ull* I, int k, int j,
                                     ull p0, ull p1, ull n1,
                                     ull p2, ull n2, ull p3, ull n3) {
    ull t0r = fma2(n3, I[j], fma2(p2, R[j], fma2(n1, I[k], mul2(p0, R[k]))));
    ull t0i = fma2(p2, I[j], fma2(p3, R[j], fma2(p0, I[k], mul2(p1, R[k]))));
    ull t1r = fma2(p1, I[j], fma2(p0, R[j], fma2(n3, I[k], mul2(n2, R[k]))));
    ull t1i = fma2(p0, I[j], fma2(n1, R[j], fma2(n2, I[k], mul2(p3, R[k]))));
    R[k] = t0r; I[k] = t0i; R[j] = t1r; I[j] = t1i;
}

// Apply SU(2) gate (v0..v3) on qubit Q to b0-packed state (8 slots, slot k = amps (k, k+8)).
template <int Q>
__device__ __forceinline__ void apply_q(ull* R, ull* I,
                                        float v0, float v1, float v2, float v3) {
    float m1 = -v1, m2 = -v2, m3 = -v3;
    if (Q == 0) {
        // lane-paired qubit: row0 coeffs on lo lane, row1 on hi lane
        ull Ar = bc2(v0), Ai = pk2(v1, m1);
        ull Br = pk2(v2, m2), Bi = bc2(v3);
        ull nAi = pk2(m1, v1), nBi = bc2(m3);
#pragma unroll
        for (int k = 0; k < 8; k++) {
            ull Rs = swap2(R[k]), Is = swap2(I[k]);
            ull nr = fma2(nBi, Is, fma2(Br, Rs, fma2(nAi, I[k], mul2(Ar, R[k]))));
            ull ni = fma2(Bi, Rs, fma2(Br, Is, fma2(Ai, R[k], mul2(Ar, I[k]))));
            R[k] = nr; I[k] = ni;
        }
    } else {
        ull p0 = bc2(v0), p1 = bc2(v1), n1 = bc2(m1);
        ull p2 = bc2(v2), n2 = bc2(m2), p3 = bc2(v3), n3 = bc2(m3);
        if (Q == 1) {
            appS(R, I, 0, 4, p0, p1, n1, p2, n2, p3, n3);
            appS(R, I, 1, 5, p0, p1, n1, p2, n2, p3, n3);
            appS(R, I, 2, 6, p0, p1, n1, p2, n2, p3, n3);
            appS(R, I, 3, 7, p0, p1, n1, p2, n2, p3, n3);
        } else if (Q == 2) {
            appS(R, I, 0, 2, p0, p1, n1, p2, n2, p3, n3);
            appS(R, I, 1, 3, p0, p1, n1, p2, n2, p3, n3);
            appS(R, I, 4, 6, p0, p1, n1, p2, n2, p3, n3);
            appS(R, I, 5, 7, p0, p1, n1, p2, n2, p3, n3);
        } else {
            appS(R, I, 0, 1, p0, p1, n1, p2, n2, p3, n3);
            appS(R, I, 2, 3, p0, p1, n1, p2, n2, p3, n3);
            appS(R, I, 4, 5, p0, p1, n1, p2, n2, p3, n3);
            appS(R, I, 6, 7, p0, p1, n1, p2, n2, p3, n3);
        }
    }
}

__global__ __launch_bounds__(128)
void pqc_kernel(const float4* __restrict__ x,
                const float* __restrict__ lmbd,
                float* __restrict__ out, int B) {
    __shared__ float4 sh_g[NGATES];
    __shared__ float sh_l[NL * NQ];
    for (int i = threadIdx.x; i < NGATES; i += blockDim.x) sh_g[i] = g_gates[i];
    for (int i = threadIdx.x; i < NL * NQ; i += blockDim.x) sh_l[i] = 0.5f * lmbd[i];
    __syncthreads();

    int t = blockIdx.x * blockDim.x + threadIdx.x;
    if (t >= B) return;

    float4 xv = x[t];
    float xq[NQ] = {xv.x, xv.y, xv.z, xv.w};

    // b0-packed state: slot k holds (amp_k, amp_{k+8})
    ull R[8], I[8];

    // ---- layer-0 fixed gates on |0000>: tensor product of gate columns 0 ----
    // SU(2) column 0 of gate g: (g.x, g.y) and (-g.z, g.w)
    {
        float4 g0 = sh_g[0], g1 = sh_g[1], g2 = sh_g[2], g3 = sh_g[3];
        float a0r = g0.x, a0i = g0.y, a1r = -g0.z, a1i = g0.w;
        float q1r[2] = {g1.x, -g1.z}, q1i[2] = {g1.y, g1.w};
        float q2r[2] = {g2.x, -g2.z}, q2i[2] = {g2.y, g2.w};
        float q3r[2] = {g3.x, -g3.z}, q3i[2] = {g3.y, g3.w};
        ull Apr = pk2(a0r, a1r), Api = pk2(a0i, a1i), nApi = pk2(-a0i, -a1i);
        float wr[4], wi[4];
#pragma unroll
        for (int b2 = 0; b2 < 2; b2++)
#pragma unroll
            for (int b3 = 0; b3 < 2; b3++) {
                wr[b2 * 2 + b3] = q2r[b2] * q3r[b3] - q2i[b2] * q3i[b3];
                wi[b2 * 2 + b3] = q2r[b2] * q3i[b3] + q2i[b2] * q3r[b3];
            }
#pragma unroll
        for (int k = 0; k < 8; k++) {
            int b1 = k >> 2, w = k & 3;
            float vr = q1r[b1] * wr[w] - q1i[b1] * wi[w];
            float vi = q1r[b1] * wi[w] + q1i[b1] * wr[w];
            ull vbr = bc2(vr), vbi = bc2(vi);
            R[k] = fma2(nApi, vbi, mul2(Apr, vbr));
            I[k] = fma2(Api, vbr, mul2(Apr, vbi));
        }
    }

    // ---- cross-layer software pipeline registers ----
    // Layer l consumes gates U(l+1) = sh_g[(l+1)*NQ + q] and lmbd row l.
    float4 u[NQ];                 // current layer's gate rows (prefetched)
    float sq[NQ], cq[NQ];         // current layer's sincos (prefetched)
#pragma unroll
    for (int q = 0; q < NQ; q++) {
        u[q] = sh_g[NQ + q];      // U(1) for layer 0
        __sincosf(sh_l[q] * xq[q], &sq[q], &cq[q]);   // lmbd row 0
    }

    // Loop l=0..NL-1: CZ_l, then V = U(l+1)*RX_l (U(NL) consumed at l=NL-1; no epilogue).
    for (int l = 0; l < NL; l++) {
        // ---- CZ ring via single-lane sign XOR (ALU pipe) ----
        // flips amps {3,6}: lo lane of slots 3,6 ; amps {9,12}: hi lane of slots 1,4
        R[3] ^= SGN_LO; I[3] ^= SGN_LO; R[6] ^= SGN_LO; I[6] ^= SGN_LO;
        R[1] ^= SGN_HI; I[1] ^= SGN_HI; R[4] ^= SGN_HI; I[4] ^= SGN_HI;

        // ---- build this layer's V = U*RX from prefetched u/s/c ----
        float vv[NQ][4];
#pragma unroll
        for (int q = 0; q < NQ; q++) {
            float s = sq[q], c = cq[q];
            float4 g = u[q];
            vv[q][0] = c * g.x + s * g.w;
            vv[q][1] = c * g.y - s * g.z;
            vv[q][2] = s * g.y + c * g.z;
            vv[q][3] = c * g.w - s * g.x;
        }

        // ---- prefetch NEXT layer's gates + sincos (latency hidden under applies) ----
        // Layer l+1 consumes U(l+2) = sh_g[(l+2)*NQ + q] and lmbd row l+1.
        {
            int ln = (l + 1 < NL) ? (l + 1) : (NL - 1);   // lmbd row, clamped
            int lg = (l + 2 <= NL) ? (l + 2) : NL;        // gate layer, clamped
#pragma unroll
            for (int q = 0; q < NQ; q++) {
                u[q] = sh_g[lg * NQ + q];                 // U(l+2); re-reads U(NL) at l=NL-1 (unused)
                __sincosf(sh_l[ln * NQ + q] * xq[q], &sq[q], &cq[q]);
            }
        }

        // ---- apply all four gates (dense fma2 streams) ----
        apply_q<0>(R, I, vv[0][0], vv[0][1], vv[0][2], vv[0][3]);
        apply_q<1>(R, I, vv[1][0], vv[1][1], vv[1][2], vv[1][3]);
        apply_q<2>(R, I, vv[2][0], vv[2][1], vv[2][2], vv[2][3]);
        apply_q<3>(R, I, vv[3][0], vv[3][1], vv[3][2], vv[3][3]);
    }

    // ---- <Z0 Z1 Z2 Z3> ----
    // slot popcount even {0,3,5,6}: lane parity (+,-); odd {1,2,4,7}: (-,+)
    ull accA = 0, accB = 0;
#pragma unroll
    for (int k = 0; k < 8; k++) {
        bool even = (k == 0 || k == 3 || k == 5 || k == 6);
        if (even) { accA = fma2(R[k], R[k], accA); accA = fma2(I[k], I[k], accA); }
        else      { accB = fma2(R[k], R[k], accB); accB = fma2(I[k], I[k], accB); }
    }
    float aL, aH, bL, bH;
    up2(accA, aL, aH); up2(accB, bL, bH);
    out[t] = (aL - aH) - (bL - bH);
}

extern "C" void kernel_launch(void* const* d_in, const int* in_sizes, int n_in,
                              void* d_out, int out_size) {
    const float* x     = (const float*)d_in[0];   // [B, 4]
    const float* theta = (const float*)d_in[1];   // [1, 108]
    const float* lmbd  = (const float*)d_in[2];   // [32]
    float* out = (float*)d_out;                   // [B, 1]
    int B = in_sizes[0] / NQ;

    precompute_gates_kernel<<<1, 64>>>(theta);
    int threads = 128;
    int blocks = (B + threads - 1) / threads;
    pqc_kernel<<<blocks, threads>>>((const float4*)x, lmbd, out, B);
}

// round 16
// speedup vs baseline: 1.0448x; 1.0448x over previous
#include <cuda_runtime.h>

#define NQ 4
#define NL 8
#define NGATES ((NL + 1) * NQ)

typedef unsigned long long ull;

// ---------- packed f32x2 helpers (Blackwell FFMA2 path) ----------
__device__ __forceinline__ ull pk2(float lo, float hi) {
    ull r; asm("mov.b64 %0, {%1,%2};" : "=l"(r) : "f"(lo), "f"(hi)); return r;
}
__device__ __forceinline__ ull bc2(float x) { return pk2(x, x); }
__device__ __forceinline__ void up2(ull v, float& lo, float& hi) {
    asm("mov.b64 {%0,%1}, %2;" : "=f"(lo), "=f"(hi) : "l"(v));
}
__device__ __forceinline__ ull fma2(ull a, ull b, ull c) {
    ull d; asm("fma.rn.f32x2 %0, %1, %2, %3;" : "=l"(d) : "l"(a), "l"(b), "l"(c)); return d;
}
__device__ __forceinline__ ull mul2(ull a, ull b) {
    ull d; asm("mul.rn.f32x2 %0, %1, %2;" : "=l"(d) : "l"(a), "l"(b)); return d;
}
__device__ __forceinline__ ull swap2(ull v) { float l, h; up2(v, l, h); return pk2(h, l); }

#define SGN_LO 0x0000000080000000ULL   // flip lo lane only
#define SGN_HI 0x8000000000000000ULL   // flip hi lane only

// SU(2) gates: U = [[a, b], [-conj(b), conj(a)]]. Store only (ar, ai, br, bi).
__device__ float4 g_gates[NGATES];

__global__ void precompute_gates_kernel(const float* __restrict__ theta) {
    int g = blockIdx.x * blockDim.x + threadIdx.x;
    if (g >= NGATES) return;
    float a = theta[g * 3 + 0];
    float b = theta[g * 3 + 1];
    float c = theta[g * 3 + 2];
    float sa, ca, sb, cb, sc, cc;
    sincosf(0.5f * a, &sa, &ca);
    sincosf(0.5f * b, &sb, &cb);
    sincosf(0.5f * c, &sc, &cc);
    float m00r = cb * ca, m00i =  sb * sa;
    float m01r = -sb * ca, m01i = -cb * sa;
    float4 o;
    o.x = m00r * cc + m00i * sc;   // u00r
    o.y = m00i * cc - m00r * sc;   // u00i
    o.z = m01r * cc + m01i * sc;   // u01r
    o.w = m01i * cc - m01r * sc;   // u01i
    g_gates[g] = o;
}

// SU(2) pair apply: V = [[v0+iv1, v2+iv3], [-v2+iv3, v0-iv1]]
__device__ __forceinline__ void appS(ull* R, ull* I, int k, int j,
                                     ull p0, ull p1, ull n1,
                                     ull p2, ull n2, ull p3, ull n3) {
    ull t0r = fma2(n3, I[j], fma2(p2, R[j], fma2(n1, I[k], mul2(p0, R[k]))));
    ull t0i = fma2(p2, I[j], fma2(p3, R[j], fma2(p0, I[k], mul2(p1, R[k]))));
    ull t1r = fma2(p1, I[j], fma2(p0, R[j], fma2(n3, I[k], mul2(n2, R[k]))));
    ull t1i = fma2(p0, I[j], fma2(n1, R[j], fma2(n2, I[k], mul2(p3, R[k]))));
    R[k] = t0r; I[k] = t0i; R[j] = t1r; I[j] = t1i;
}

// Apply SU(2) gate (v0..v3) on qubit Q to b0-packed state (8 slots, slot k = amps (k, k+8)).
template <int Q>
__device__ __forceinline__ void apply_q(ull* R, ull* I,
                                        float v0, float v1, float v2, float v3) {
    float m1 = -v1, m2 = -v2, m3 = -v3;
    if (Q == 0) {
        // lane-paired qubit: row0 coeffs on lo lane, row1 on hi lane
        ull Ar = bc2(v0), Ai = pk2(v1, m1);
        ull Br = pk2(v2, m2), Bi = bc2(v3);
        ull nAi = pk2(m1, v1), nBi = bc2(m3);
#pragma unroll
        for (int k = 0; k < 8; k++) {
            ull Rs = swap2(R[k]), Is = swap2(I[k]);
            ull nr = fma2(nBi, Is, fma2(Br, Rs, fma2(nAi, I[k], mul2(Ar, R[k]))));
            ull ni = fma2(Bi, Rs, fma2(Br, Is, fma2(Ai, R[k], mul2(Ar, I[k]))));
            R[k] = nr; I[k] = ni;
        }
    } else {
        ull p0 = bc2(v0), p1 = bc2(v1), n1 = bc2(m1);
        ull p2 = bc2(v2), n2 = bc2(m2), p3 = bc2(v3), n3 = bc2(m3);
        if (Q == 1) {
            appS(R, I, 0, 4, p0, p1, n1, p2, n2, p3, n3);
            appS(R, I, 1, 5, p0, p1, n1, p2, n2, p3, n3);
            appS(R, I, 2, 6, p0, p1, n1, p2, n2, p3, n3);
            appS(R, I, 3, 7, p0, p1, n1, p2, n2, p3, n3);
        } else if (Q == 2) {
            appS(R, I, 0, 2, p0, p1, n1, p2, n2, p3, n3);
            appS(R, I, 1, 3, p0, p1, n1, p2, n2, p3, n3);
            appS(R, I, 4, 6, p0, p1, n1, p2, n2, p3, n3);
            appS(R, I, 5, 7, p0, p1, n1, p2, n2, p3, n3);
        } else {
            appS(R, I, 0, 1, p0, p1, n1, p2, n2, p3, n3);
            appS(R, I, 2, 3, p0, p1, n1, p2, n2, p3, n3);
            appS(R, I, 4, 5, p0, p1, n1, p2, n2, p3, n3);
            appS(R, I, 6, 7, p0, p1, n1, p2, n2, p3, n3);
        }
    }
}

__global__ __launch_bounds__(128)
void pqc_kernel(const float4* __restrict__ x,
                const float* __restrict__ lmbd,
                float* __restrict__ out, int B) {
    __shared__ float4 sh_g[NGATES];
    __shared__ float sh_l[NL * NQ];
    for (int i = threadIdx.x; i < NGATES; i += blockDim.x) sh_g[i] = g_gates[i];
    for (int i = threadIdx.x; i < NL * NQ; i += blockDim.x) sh_l[i] = 0.5f * lmbd[i];
    __syncthreads();

    int t = blockIdx.x * blockDim.x + threadIdx.x;
    if (t >= B) return;

    float4 xv = x[t];
    float xq[NQ] = {xv.x, xv.y, xv.z, xv.w};

    // b0-packed state: slot k holds (amp_k, amp_{k+8})
    ull R[8], I[8];

    // ---- layer-0 fixed gates on |0000>: tensor product of gate columns 0 ----
    // SU(2) column 0 of gate g: (g.x, g.y) and (-g.z, g.w)
    {
        float4 g0 = sh_g[0], g1 = sh_g[1], g2 = sh_g[2], g3 = sh_g[3];
        float a0r = g0.x, a0i = g0.y, a1r = -g0.z, a1i = g0.w;
        float q1r[2] = {g1.x, -g1.z}, q1i[2] = {g1.y, g1.w};
        float q2r[2] = {g2.x, -g2.z}, q2i[2] = {g2.y, g2.w};
        float q3r[2] = {g3.x, -g3.z}, q3i[2] = {g3.y, g3.w};
        ull Apr = pk2(a0r, a1r), Api = pk2(a0i, a1i), nApi = pk2(-a0i, -a1i);
        float wr[4], wi[4];
#pragma unroll
        for (int b2 = 0; b2 < 2; b2++)
#pragma unroll
            for (int b3 = 0; b3 < 2; b3++) {
                wr[b2 * 2 + b3] = q2r[b2] * q3r[b3] - q2i[b2] * q3i[b3];
                wi[b2 * 2 + b3] = q2r[b2] * q3i[b3] + q2i[b2] * q3r[b3];
            }
#pragma unroll
        for (int k = 0; k < 8; k++) {
            int b1 = k >> 2, w = k & 3;
            float vr = q1r[b1] * wr[w] - q1i[b1] * wi[w];
            float vi = q1r[b1] * wi[w] + q1i[b1] * wr[w];
            ull vbr = bc2(vr), vbi = bc2(vi);
            R[k] = fma2(nApi, vbi, mul2(Apr, vbr));
            I[k] = fma2(Api, vbr, mul2(Apr, vbi));
        }
    }

    // Loop l=0..NL-1: CZ_l, then V = U(l+1)*RX_l (U(NL) consumed at l=NL-1; no epilogue).
    for (int l = 0; l < NL; l++) {
        // ---- CZ ring via single-lane sign XOR (ALU pipe) ----
        // flips amps {3,6}: lo lane of slots 3,6 ; amps {9,12}: hi lane of slots 1,4
        R[3] ^= SGN_LO; I[3] ^= SGN_LO; R[6] ^= SGN_LO; I[6] ^= SGN_LO;
        R[1] ^= SGN_HI; I[1] ^= SGN_HI; R[4] ^= SGN_HI; I[4] ^= SGN_HI;

        const float4* gl = &sh_g[(l + 1) * NQ];
        const float* ll = &sh_l[l * NQ];

#pragma unroll
        for (int q = 0; q < NQ; q++) {
            float4 u = gl[q];            // one LDS.128: (u00r,u00i,u01r,u01i)
            float s, c;
            __sincosf(ll[q] * xq[q], &s, &c);
            // V = U*RX (SU(2)): only row 0 needed
            float v0 = c * u.x + s * u.w, v1 = c * u.y - s * u.z;
            float v2 = s * u.y + c * u.z, v3 = c * u.w - s * u.x;
            if (q == 0)      apply_q<0>(R, I, v0, v1, v2, v3);
            else if (q == 1) apply_q<1>(R, I, v0, v1, v2, v3);
            else if (q == 2) apply_q<2>(R, I, v0, v1, v2, v3);
            else             apply_q<3>(R, I, v0, v1, v2, v3);
        }
    }

    // ---- <Z0 Z1 Z2 Z3> ----
    // slot popcount even {0,3,5,6}: lane parity (+,-); odd {1,2,4,7}: (-,+)
    ull accA = 0, accB = 0;
#pragma unroll
    for (int k = 0; k < 8; k++) {
        bool even = (k == 0 || k == 3 || k == 5 || k == 6);
        if (even) { accA = fma2(R[k], R[k], accA); accA = fma2(I[k], I[k], accA); }
        else      { accB = fma2(R[k], R[k], accB); accB = fma2(I[k], I[k], accB); }
    }
    float aL, aH, bL, bH;
    up2(accA, aL, aH); up2(accB, bL, bH);
    out[t] = (aL - aH) - (bL - bH);
}

extern "C" void kernel_launch(void* const* d_in, const int* in_sizes, int n_in,
                              void* d_out, int out_size) {
    const float* x     = (const float*)d_in[0];   // [B, 4]
    const float* theta = (const float*)d_in[1];   // [1, 108]
    const float* lmbd  = (const float*)d_in[2];   // [32]
    float* out = (float*)d_out;                   // [B, 1]
    int B = in_sizes[0] / NQ;

    precompute_gates_kernel<<<1, 64>>>(theta);
    int threads = 128;
    int blocks = (B + threads - 1) / threads;
    pqc_kernel<<<blocks, threads>>>((const float4*)x, lmbd, out, B);
}